// round 17
// baseline (speedup 1.0000x reference)
#include <cuda_runtime.h>
#include <cuda_fp16.h>
#include <math.h>
#include <stdint.h>

#define N_TOK 4096
#define DMODEL 1024

// ---------------------------------------------------------------------------
// Scratch (device globals)
// ---------------------------------------------------------------------------
__device__ __half g_xh[(size_t)N_TOK * DMODEL];              // [4096, 1024]
__device__ __half g_wh[(size_t)3 * DMODEL * DMODEL];         // [3072, 1024]
__device__ __half g_qh[(size_t)N_TOK * DMODEL];              // [4096, 1024] (pre-scaled 1/32)
__device__ __half g_kh[(size_t)N_TOK * DMODEL];              // [4096, 1024]
__device__ __half g_vh[(size_t)N_TOK * DMODEL];              // [4096, 1024]
__device__ __half g_sh[(size_t)N_TOK * N_TOK];               // [4096, 4096] P = exp(scores)
__device__ float  g_psum[(size_t)N_TOK * 64];                // per-CTA row partial sums

// ---------------------------------------------------------------------------
// PTX helpers (baseline sm_80+ instructions only)
// ---------------------------------------------------------------------------
__device__ __forceinline__ uint32_t smem_u32(const void* p) {
    uint32_t a;
    asm("{ .reg .u64 t; cvta.to.shared.u64 t, %1; cvt.u32.u64 %0, t; }" : "=r"(a) : "l"(p));
    return a;
}
__device__ __forceinline__ void cp_async16(uint32_t saddr, const void* gptr) {
    asm volatile("cp.async.cg.shared.global [%0], [%1], 16;" :: "r"(saddr), "l"(gptr) : "memory");
}
__device__ __forceinline__ void cp_commit() {
    asm volatile("cp.async.commit_group;" ::: "memory");
}
__device__ __forceinline__ void cp_wait1() {
    asm volatile("cp.async.wait_group 1;" ::: "memory");
}
__device__ __forceinline__ void ldsm_x4(uint32_t& r0, uint32_t& r1, uint32_t& r2, uint32_t& r3,
                                        uint32_t addr) {
    asm volatile("ldmatrix.sync.aligned.m8n8.x4.shared.b16 {%0,%1,%2,%3}, [%4];"
                 : "=r"(r0), "=r"(r1), "=r"(r2), "=r"(r3) : "r"(addr));
}
__device__ __forceinline__ void ldsm_x4_t(uint32_t& r0, uint32_t& r1, uint32_t& r2, uint32_t& r3,
                                          uint32_t addr) {
    asm volatile("ldmatrix.sync.aligned.m8n8.x4.trans.shared.b16 {%0,%1,%2,%3}, [%4];"
                 : "=r"(r0), "=r"(r1), "=r"(r2), "=r"(r3) : "r"(addr));
}
__device__ __forceinline__ void mma_f16(float& c0, float& c1, float& c2, float& c3,
                                        uint32_t a0, uint32_t a1, uint32_t a2, uint32_t a3,
                                        uint32_t b0, uint32_t b1) {
    asm volatile(
        "mma.sync.aligned.m16n8k16.row.col.f32.f16.f16.f32 "
        "{%0,%1,%2,%3}, {%4,%5,%6,%7}, {%8,%9}, {%0,%1,%2,%3};"
        : "+f"(c0), "+f"(c1), "+f"(c2), "+f"(c3)
        : "r"(a0), "r"(a1), "r"(a2), "r"(a3), "r"(b0), "r"(b1));
}
#define SW128(b)  ((b) ^ (((b) >> 3) & 0x70))   // 128B-row swizzle (rows of 64 fp16)
#define SWZ256(b) ((b) ^ (((b) >> 4) & 0x70))   // 256B-row swizzle (rows of 128 fp16)

// ---------------------------------------------------------------------------
// Persistent fp16 tensor-core GEMM: CTA tile 128x128, BK=64, 3-stage cp.async,
// 4 warps (2x2), warp tile 64x64, fragment double-buffering, 2 CTAs/SM.
// Each CTA loops tile += gridDim.x over numTiles (kills wave quantization).
// BT=0: NT (B[N,K], K contiguous).  BT=1: NN (B[K,N] row-major, ldmatrix.trans)
// MODE 1: C(fp32) = A@B / rowsum; rowsum param = psum[4096][64] partials,
//         reduced per-CTA into smem during the pipeline prologue.
// MODE 2: QKV fused epilogue: region 0 -> qh*(1/32), 1 -> kh, 2 -> vh (fp16)
// MODE 3: P(fp16) = exp(A@B^T) via qh; per-CTA row partial sums -> C (psum)
// ---------------------------------------------------------------------------
#define STAGES 3
#define STAGE_BYTES 32768            // A 16KB + B 16KB
#define GEMM_SMEM_BYTES (STAGES * STAGE_BYTES + 512)

template<int MODE, int BT>
__global__ __launch_bounds__(128, 2)
void gemm_tc(const uint16_t* __restrict__ A,
             const uint16_t* __restrict__ B,
             float* __restrict__ C, int Kb, int ldc,
             const float* __restrict__ rowsum,
             uint16_t* __restrict__ qh,
             uint16_t* __restrict__ kh,
             uint16_t* __restrict__ vh,
             int nx, int numTiles)
{
    extern __shared__ char smem[];
    const uint32_t sbase = smem_u32(smem);
    float* rowinv = reinterpret_cast<float*>(smem + STAGES * STAGE_BYTES);

    const int tid  = threadIdx.x;
    const int wid  = tid >> 5;
    const int lane = tid & 31;
    const int warp_m = wid >> 1;     // 0..1
    const int warp_n = wid & 1;      // 0..1
    const int T  = Kb >> 6;

    // ---- hoisted per-thread fragment base addresses (swizzled once) ----
    const uint32_t a_row = (uint32_t)(warp_m * 64 + (lane & 15)) * 128;
    const uint32_t a_chk = (uint32_t)(lane >> 4) * 16;
    uint32_t a_base[4];
#pragma unroll
    for (int mi = 0; mi < 4; mi++)
        a_base[mi] = SW128(a_row + (uint32_t)(mi * 2048) + a_chk);

    uint32_t b_base[4];
    if (BT) {
        const uint32_t bt_krow   = (uint32_t)((lane & 7) + ((lane >> 3) & 1) * 8);
        const uint32_t bt_coloff = (uint32_t)(warp_n * 128 + ((lane >> 4) & 1) * 16);
#pragma unroll
        for (int np = 0; np < 4; np++)
            b_base[np] = SWZ256(bt_krow * 256 + bt_coloff + (uint32_t)(np * 32));
    } else {
        const uint32_t b_row = (uint32_t)(warp_n * 64 + (lane & 7) + ((lane >> 4) & 1) * 8) * 128;
        const uint32_t b_chk = (uint32_t)((lane >> 3) & 1) * 16;
#pragma unroll
        for (int np = 0; np < 4; np++)
            b_base[np] = SW128(b_row + (uint32_t)(np * 2048) + b_chk);
    }
    const uint32_t bstep = BT ? 4096u : 32u;

    // ================= persistent tile loop =================
    for (int t = blockIdx.x; t < numTiles; t += gridDim.x) {
        const int bx = t % nx;
        const int by = t / nx;
        const int m0 = by * 128;
        const int n0 = bx * 128;

        const uint16_t* Ab = A + (size_t)m0 * Kb;
        const uint16_t* Bb = BT ? (B + n0) : (B + (size_t)n0 * Kb);

        // protect stage buffers + rowinv from the previous tile's readers
        __syncthreads();

        float acc[4][8][4];
#pragma unroll
        for (int mi = 0; mi < 4; mi++)
#pragma unroll
            for (int ni = 0; ni < 8; ni++)
#pragma unroll
                for (int e = 0; e < 4; e++) acc[mi][ni][e] = 0.0f;

        // -------- prologue: issue stages 0..1 --------
#pragma unroll
        for (int p = 0; p < 2; p++) {
            const uint32_t sa = sbase + p * STAGE_BYTES;
            const uint32_t sb = sa + 16384;
            const int k0 = p << 6;
#pragma unroll
            for (int j = 0; j < 8; j++) {
                int chunk = tid + j * 128;
                int r = chunk >> 3, c16 = chunk & 7;
                cp_async16(sa + SW128((uint32_t)(r * 128 + c16 * 16)),
                           Ab + (size_t)r * Kb + k0 + c16 * 8);
            }
            if (BT) {
#pragma unroll
                for (int j = 0; j < 8; j++) {
                    int chunk = tid + j * 128;
                    int r = chunk >> 4, c16 = chunk & 15;   // 64 rows x 16 chunks
                    cp_async16(sb + SWZ256((uint32_t)(r * 256 + c16 * 16)),
                               Bb + (size_t)(k0 + r) * DMODEL + c16 * 8);
                }
            } else {
#pragma unroll
                for (int j = 0; j < 8; j++) {
                    int chunk = tid + j * 128;
                    int r = chunk >> 3, c16 = chunk & 7;
                    cp_async16(sb + SW128((uint32_t)(r * 128 + c16 * 16)),
                               Bb + (size_t)r * Kb + k0 + c16 * 8);
                }
            }
            cp_commit();
        }

        // MODE 1: reduce this tile's 128 row partial-sums while pipeline fills.
        if (MODE == 1) {
            const float* p = rowsum + (size_t)(m0 + tid) * 64;
            float s = 0.0f;
#pragma unroll
            for (int j = 0; j < 16; j++) {
                float4 v = *reinterpret_cast<const float4*>(p + j * 4);
                s += v.x + v.y + v.z + v.w;
            }
            rowinv[tid] = 1.0f / s;
        }

        uint32_t afr[2][4][4];
        uint32_t bfr[2][8][2];

        // -------- mainloop --------
        for (int i = 0; i < T; i++) {
            cp_wait1();
            __syncthreads();

            const uint32_t sa = sbase + (i % STAGES) * STAGE_BYTES;
            const uint32_t sb = sa + 16384;

            // load kk=0 fragments first (critical path to MMAs)
#pragma unroll
            for (int mi = 0; mi < 4; mi++)
                ldsm_x4(afr[0][mi][0], afr[0][mi][1], afr[0][mi][2], afr[0][mi][3],
                        sa + a_base[mi]);
#pragma unroll
            for (int np = 0; np < 4; np++) {
                uint32_t r0, r1, r2, r3;
                if (BT) ldsm_x4_t(r0, r1, r2, r3, sb + b_base[np]);
                else    ldsm_x4  (r0, r1, r2, r3, sb + b_base[np]);
                bfr[0][np * 2 + 0][0] = r0; bfr[0][np * 2 + 0][1] = r1;
                bfr[0][np * 2 + 1][0] = r2; bfr[0][np * 2 + 1][1] = r3;
            }

            // issue prefetch for tile i+2 into stage (i+2)%3
            if (i + 2 < T) {
                const uint32_t pa = sbase + ((i + 2) % STAGES) * STAGE_BYTES;
                const uint32_t pb = pa + 16384;
                const int k0 = (i + 2) << 6;
#pragma unroll
                for (int j = 0; j < 8; j++) {
                    int chunk = tid + j * 128;
                    int r = chunk >> 3, c16 = chunk & 7;
                    cp_async16(pa + SW128((uint32_t)(r * 128 + c16 * 16)),
                               Ab + (size_t)r * Kb + k0 + c16 * 8);
                }
                if (BT) {
#pragma unroll
                    for (int j = 0; j < 8; j++) {
                        int chunk = tid + j * 128;
                        int r = chunk >> 4, c16 = chunk & 15;
                        cp_async16(pb + SWZ256((uint32_t)(r * 256 + c16 * 16)),
                                   Bb + (size_t)(k0 + r) * DMODEL + c16 * 8);
                    }
                } else {
#pragma unroll
                    for (int j = 0; j < 8; j++) {
                        int chunk = tid + j * 128;
                        int r = chunk >> 3, c16 = chunk & 7;
                        cp_async16(pb + SW128((uint32_t)(r * 128 + c16 * 16)),
                                   Bb + (size_t)r * Kb + k0 + c16 * 8);
                    }
                }
            }
            cp_commit();

#pragma unroll
            for (int kk = 0; kk < 4; kk++) {
                const int cur = kk & 1, nxt = cur ^ 1;
                if (kk < 3) {
                    const uint32_t aoff = (uint32_t)((kk + 1) * 32);
                    const uint32_t boff = (uint32_t)(kk + 1) * bstep;
#pragma unroll
                    for (int mi = 0; mi < 4; mi++)
                        ldsm_x4(afr[nxt][mi][0], afr[nxt][mi][1], afr[nxt][mi][2], afr[nxt][mi][3],
                                sa + (a_base[mi] ^ aoff));
#pragma unroll
                    for (int np = 0; np < 4; np++) {
                        uint32_t r0, r1, r2, r3;
                        if (BT) ldsm_x4_t(r0, r1, r2, r3, sb + (b_base[np] ^ boff));
                        else    ldsm_x4  (r0, r1, r2, r3, sb + (b_base[np] ^ boff));
                        bfr[nxt][np * 2 + 0][0] = r0; bfr[nxt][np * 2 + 0][1] = r1;
                        bfr[nxt][np * 2 + 1][0] = r2; bfr[nxt][np * 2 + 1][1] = r3;
                    }
                }
#pragma unroll
                for (int mi = 0; mi < 4; mi++)
#pragma unroll
                    for (int ni = 0; ni < 8; ni++)
                        mma_f16(acc[mi][ni][0], acc[mi][ni][1], acc[mi][ni][2], acc[mi][ni][3],
                                afr[cur][mi][0], afr[cur][mi][1], afr[cur][mi][2], afr[cur][mi][3],
                                bfr[cur][ni][0], bfr[cur][ni][1]);
            }
        }

        // -------- epilogue --------
        const int col_off = warp_n * 64 + (lane & 3) * 2;
        const int row_base = m0 + warp_m * 64 + (lane >> 2);

#pragma unroll
        for (int mi = 0; mi < 4; mi++) {
            const int r0 = row_base + mi * 16;
            const int r1 = r0 + 8;
            if (MODE == 2) {
                const int region = n0 >> 10;
                const int nc0 = (n0 & 1023) + col_off;
                uint16_t* dst = (region == 0) ? qh : (region == 1) ? kh : vh;
                const float qs = (region == 0) ? 0.03125f : 1.0f;   // fold 1/32 into q
#pragma unroll
                for (int ni = 0; ni < 8; ni++) {
                    const int c = nc0 + ni * 8;
                    __half2 h0 = __floats2half2_rn(acc[mi][ni][0] * qs, acc[mi][ni][1] * qs);
                    __half2 h1 = __floats2half2_rn(acc[mi][ni][2] * qs, acc[mi][ni][3] * qs);
                    *reinterpret_cast<uint32_t*>(dst + (size_t)r0 * DMODEL + c) =
                        *reinterpret_cast<uint32_t*>(&h0);
                    *reinterpret_cast<uint32_t*>(dst + (size_t)r1 * DMODEL + c) =
                        *reinterpret_cast<uint32_t*>(&h1);
                }
            } else if (MODE == 3) {
                // P = exp(scores); deterministic per-tile row partial sums -> C (psum)
                uint16_t* C0 = qh + (size_t)r0 * ldc + n0;
                uint16_t* C1 = qh + (size_t)r1 * ldc + n0;
                float sum0 = 0.0f, sum1 = 0.0f;
#pragma unroll
                for (int ni = 0; ni < 8; ni++) {
                    const int c = col_off + ni * 8;
                    float e0 = __expf(acc[mi][ni][0]);
                    float e1 = __expf(acc[mi][ni][1]);
                    float e2 = __expf(acc[mi][ni][2]);
                    float e3 = __expf(acc[mi][ni][3]);
                    sum0 += e0 + e1;
                    sum1 += e2 + e3;
                    __half2 h0 = __floats2half2_rn(e0, e1);
                    __half2 h1 = __floats2half2_rn(e2, e3);
                    *reinterpret_cast<uint32_t*>(C0 + c) = *reinterpret_cast<uint32_t*>(&h0);
                    *reinterpret_cast<uint32_t*>(C1 + c) = *reinterpret_cast<uint32_t*>(&h1);
                }
                sum0 += __shfl_xor_sync(0xFFFFFFFFu, sum0, 1);
                sum0 += __shfl_xor_sync(0xFFFFFFFFu, sum0, 2);
                sum1 += __shfl_xor_sync(0xFFFFFFFFu, sum1, 1);
                sum1 += __shfl_xor_sync(0xFFFFFFFFu, sum1, 2);
                if ((lane & 3) == 0) {
                    const int slot = bx * 2 + warp_n;    // 0..63
                    C[(size_t)r0 * 64 + slot] = sum0;
                    C[(size_t)r1 * 64 + slot] = sum1;
                }
            } else {  // MODE 1
                const float sc0 = rowinv[r0 - m0];
                const float sc1 = rowinv[r1 - m0];
                float* C0 = C + (size_t)r0 * ldc + n0;
                float* C1 = C + (size_t)r1 * ldc + n0;
#pragma unroll
                for (int ni = 0; ni < 8; ni++) {
                    const int c = col_off + ni * 8;
                    *reinterpret_cast<float2*>(C0 + c) =
                        make_float2(acc[mi][ni][0] * sc0, acc[mi][ni][1] * sc0);
                    *reinterpret_cast<float2*>(C1 + c) =
                        make_float2(acc[mi][ni][2] * sc1, acc[mi][ni][3] * sc1);
                }
            }
        }
    }
}

// ---------------------------------------------------------------------------
// Merged fp32 -> fp16 convert for x, wq, wk, wv (8 elems/thread)
// ---------------------------------------------------------------------------
__global__ __launch_bounds__(256) void convert_all(
    const float* __restrict__ x,  const float* __restrict__ wq,
    const float* __restrict__ wk, const float* __restrict__ wv,
    __half* __restrict__ xh, __half* __restrict__ wh)
{
    const size_t NE1 = (size_t)N_TOK * DMODEL;    // 4 Mi
    const size_t NEW = (size_t)DMODEL * DMODEL;   // 1 Mi
    size_t idx = ((size_t)blockIdx.x * 256 + threadIdx.x) * 8;

    const float* src;
    __half* dst;
    size_t off;
    if (idx < NE1)                 { src = x;  dst = xh; off = idx; }
    else if (idx < NE1 + NEW)      { src = wq; dst = wh;            off = idx - NE1; }
    else if (idx < NE1 + 2 * NEW)  { src = wk; dst = wh + NEW;      off = idx - NE1 - NEW; }
    else                           { src = wv; dst = wh + 2 * NEW;  off = idx - NE1 - 2 * NEW; }

    float4 a = *reinterpret_cast<const float4*>(src + off);
    float4 b = *reinterpret_cast<const float4*>(src + off + 4);
    __half2 h0 = __floats2half2_rn(a.x, a.y);
    __half2 h1 = __floats2half2_rn(a.z, a.w);
    __half2 h2 = __floats2half2_rn(b.x, b.y);
    __half2 h3 = __floats2half2_rn(b.z, b.w);
    uint4 u;
    u.x = *reinterpret_cast<uint32_t*>(&h0);
    u.y = *reinterpret_cast<uint32_t*>(&h1);
    u.z = *reinterpret_cast<uint32_t*>(&h2);
    u.w = *reinterpret_cast<uint32_t*>(&h3);
    *reinterpret_cast<uint4*>(dst + off) = u;
}

// ---------------------------------------------------------------------------
extern "C" void kernel_launch(void* const* d_in, const int* in_sizes, int n_in,
                              void* d_out, int out_size)
{
    const float* x  = (const float*)d_in[0];
    const float* wq = (const float*)d_in[1];
    const float* wk = (const float*)d_in[2];
    const float* wv = (const float*)d_in[3];
    float* out = (float*)d_out;

    __half *xh, *wh, *qh, *kh, *vh, *sh;
    float *ps;
    cudaGetSymbolAddress((void**)&xh,  g_xh);
    cudaGetSymbolAddress((void**)&wh,  g_wh);
    cudaGetSymbolAddress((void**)&qh,  g_qh);
    cudaGetSymbolAddress((void**)&kh,  g_kh);
    cudaGetSymbolAddress((void**)&vh,  g_vh);
    cudaGetSymbolAddress((void**)&sh,  g_sh);
    cudaGetSymbolAddress((void**)&ps,  g_psum);

    cudaFuncSetAttribute(gemm_tc<1,1>, cudaFuncAttributeMaxDynamicSharedMemorySize, GEMM_SMEM_BYTES);
    cudaFuncSetAttribute(gemm_tc<2,0>, cudaFuncAttributeMaxDynamicSharedMemorySize, GEMM_SMEM_BYTES);
    cudaFuncSetAttribute(gemm_tc<3,0>, cudaFuncAttributeMaxDynamicSharedMemorySize, GEMM_SMEM_BYTES);

    dim3 blk128(128);
    dim3 blk256(256);
    const int PERSIST = 296;   // 148 SMs x 2 CTAs

    // merged fp16 casts: 7 Mi elems / 8 per thread / 256 per block
    convert_all<<<3584, blk256>>>(x, wq, wk, wv, xh, wh);

    // QKV: fp16, K=1024, fused fp16 epilogue -> qh(/32), kh, vh  (768 tiles, persistent)
    gemm_tc<2,0><<<PERSIST, blk128, GEMM_SMEM_BYTES>>>(
        (const uint16_t*)xh, (const uint16_t*)wh, nullptr, DMODEL, 0,
        nullptr, (uint16_t*)qh, (uint16_t*)kh, (uint16_t*)vh,
        3 * DMODEL / 128, (3 * DMODEL / 128) * (N_TOK / 128));

    // scores+exp: sh(fp16) = exp(qh @ kh^T), psum partials  (1024 tiles, persistent)
    gemm_tc<3,0><<<PERSIST, blk128, GEMM_SMEM_BYTES>>>(
        (const uint16_t*)qh, (const uint16_t*)kh, ps, DMODEL, N_TOK,
        nullptr, (uint16_t*)sh, nullptr, nullptr,
        N_TOK / 128, (N_TOK / 128) * (N_TOK / 128));

    // out = (sh @ vh) / rowsum — fp16 NN; rowsum partials reduced in-kernel (256 tiles)
    gemm_tc<1,1><<<256, blk128, GEMM_SMEM_BYTES>>>(
        (const uint16_t*)sh, (const uint16_t*)vh, out, N_TOK, DMODEL,
        ps, nullptr, nullptr, nullptr,
        DMODEL / 128, (DMODEL / 128) * (N_TOK / 128));
}